// round 9
// baseline (speedup 1.0000x reference)
#include <cuda_runtime.h>
#include <cstdint>

#define MAX_E    131072
#define NTYPE    10
#define NB_HIST  32
#define GRIDX    29
#define TILE_M   64

__device__ int g_part[NB_HIST][NTYPE];
__device__ int g_off[NTYPE + 1];
__device__ int g_cursor[NTYPE];
__device__ int g_perm[MAX_E];

typedef unsigned long long u64;
typedef unsigned int u32;

// ---------------- helpers ----------------

__device__ __forceinline__ u32 smem_u32(const void* p) {
    u32 a;
    asm("{ .reg .u64 t; cvta.to.shared.u64 t, %1; cvt.u32.u64 %0, t; }" : "=r"(a) : "l"(p));
    return a;
}

__device__ __forceinline__ u32 to_tf32(float x) {
    u32 y;
    asm("cvt.rna.tf32.f32 %0, %1;" : "=r"(y) : "f"(x));
    return y;
}

__device__ __forceinline__ void mma8(float* d, u32 a0, u32 a1, u32 a2, u32 a3,
                                     u32 b0, u32 b1) {
    asm volatile(
        "mma.sync.aligned.m16n8k8.row.col.f32.tf32.tf32.f32 "
        "{%0,%1,%2,%3}, {%4,%5,%6,%7}, {%8,%9}, {%0,%1,%2,%3};"
        : "+f"(d[0]), "+f"(d[1]), "+f"(d[2]), "+f"(d[3])
        : "r"(a0), "r"(a1), "r"(a2), "r"(a3), "r"(b0), "r"(b1));
}

// ldmatrix x4: four 8x8 b32-tiles -> exact m16n8k8 tf32 A fragment
__device__ __forceinline__ void ldm4(u32& a0, u32& a1, u32& a2, u32& a3, u32 addr) {
    asm volatile(
        "ldmatrix.sync.aligned.m8n8.x4.shared.b16 {%0,%1,%2,%3}, [%4];"
        : "=r"(a0), "=r"(a1), "=r"(a2), "=r"(a3) : "r"(addr));
}

#define CP_ASYNC16(dst, src) \
    asm volatile("cp.async.cg.shared.global [%0], [%1], 16;" :: "r"(dst), "l"(src) : "memory")
#define CP_COMMIT() asm volatile("cp.async.commit_group;" ::: "memory")
#define CP_WAIT1()  asm volatile("cp.async.wait_group 1;" ::: "memory")
#define CP_WAIT0()  asm volatile("cp.async.wait_group 0;" ::: "memory")

// tanh via (e^{2x}-1)/(e^{2x}+1), ex2/rcp approx; rel err ~1e-6
__device__ __forceinline__ float tanh_ex(float x) {
    x = fminf(fmaxf(x, -15.0f), 15.0f);
    float t;
    asm("ex2.approx.f32 %0, %1;" : "=f"(t) : "f"(x * 2.8853900817779268f));
    float r;
    asm("rcp.approx.f32 %0, %1;" : "=f"(r) : "f"(t + 1.0f));
    return (t - 1.0f) * r;
}

// ---------------- sort kernels ----------------

__global__ void k_hist(const int* __restrict__ bij, int n) {
    __shared__ int s[NTYPE];
    int tid = threadIdx.x;
    if (tid < NTYPE) s[tid] = 0;
    __syncthreads();
    int lane = tid & 31;
    int stride = gridDim.x * blockDim.x;
    int base = blockIdx.x * blockDim.x + tid;
    int iters = (n + stride - 1) / stride;
    for (int it = 0; it < iters; it++) {
        int i = base + it * stride;
        bool valid = (i < n);
        unsigned act = __ballot_sync(0xffffffffu, valid);
        if (valid) {
            int t = bij[i];
            unsigned m = __match_any_sync(act, t);
            int leader = __ffs(m) - 1;
            if (lane == leader) atomicAdd(&s[t], __popc(m));
        }
    }
    __syncthreads();
    if (tid < NTYPE) g_part[blockIdx.x][tid] = s[tid];
}

__global__ void k_prefix() {
    __shared__ int c[NTYPE];
    int t = threadIdx.x;
    if (t < NTYPE) {
        int s = 0;
        #pragma unroll
        for (int b = 0; b < NB_HIST; b++) s += g_part[b][t];
        c[t] = s;
    }
    __syncthreads();
    if (t == 0) {
        int acc = 0;
        for (int i = 0; i < NTYPE; i++) {
            g_off[i] = acc;
            g_cursor[i] = acc;
            acc += c[i];
        }
        g_off[NTYPE] = acc;
    }
}

__global__ void k_scatter(const int* __restrict__ bij, int n) {
    __shared__ int s_cnt[NTYPE], s_base[NTYPE];
    int tid = threadIdx.x;
    int lane = tid & 31;
    if (tid < NTYPE) s_cnt[tid] = 0;
    __syncthreads();
    int i = blockIdx.x * blockDim.x + tid;
    bool valid = (i < n);
    unsigned act = __ballot_sync(0xffffffffu, valid);
    int t = 0, lpos = 0;
    if (valid) {
        t = bij[i];
        unsigned m = __match_any_sync(act, t);
        int leader = __ffs(m) - 1;
        unsigned lt;
        asm("mov.u32 %0, %%lanemask_lt;" : "=r"(lt));
        int rank = __popc(m & lt);
        int bse = 0;
        if (lane == leader) bse = atomicAdd(&s_cnt[t], __popc(m));
        bse = __shfl_sync(act, bse, leader);
        lpos = bse + rank;
    }
    __syncthreads();
    if (tid < NTYPE)
        s_base[tid] = s_cnt[tid] ? atomicAdd(&g_cursor[tid], s_cnt[tid]) : 0;
    __syncthreads();
    if (valid) g_perm[s_base[t] + lpos] = i;
}

// ---------------- tensor-core GEMM (mma.sync tf32 + ldmatrix) ----------------
// Grid (GRIDX, NTYPE) = 290 blocks, 256 threads = 8 warps, 2 CTAs/SM.
// Per 64-edge tile: D[64x128] = A[64x64] x B[128x64]^T,
//   B rows 0-63 = W_t, 64-127 = lin_w.
// Warp w: mg = w>>2 -> edges [mg*32, +32); ng = w&3 -> W cols [ng*16, +16)
//   AND L cols [64+ng*16, +16) -> thread-local tanh+combine.
// A pipeline: cp.async raw -> in-place tf32 cvt (each thread re-rounds the
//   16 floats it gathered) -> ldmatrix.x4 fragment loads (1 instr / kc).
// Padded ASTRIDE=68 floats: ldmatrix row banks 4*row mod 32 -> conflict-free.
//
// smem floats: A0@0 (64x68), A1@4352, B@8704 (128x68), bias@17408,
//              perm@17472 (2 x 64 ints).

#define ASTRIDE   68
#define F_A1      4352
#define F_B       8704
#define F_BIAS    17408
#define F_PERM    17472
#define SMEM_BYTES ((F_PERM + 128) * 4)

__global__ __launch_bounds__(256, 2)
void k_gemm(const float* __restrict__ desc,
            const float* __restrict__ layer1,
            const float* __restrict__ lin_w,
            const float* __restrict__ lin_b,
            float* __restrict__ out)
{
    extern __shared__ float sm[];
    float* B_s    = sm + F_B;
    float* sBias  = sm + F_BIAS;
    int*   sPermB = (int*)(sm + F_PERM);

    const int t    = blockIdx.y;
    const int tid  = threadIdx.x;
    const int lane = tid & 31;
    const int warp = tid >> 5;
    const int g    = lane >> 2;   // fragment row group
    const int tig  = lane & 3;    // thread-in-group
    const int mg   = warp >> 2;   // edge group (32 edges)
    const int ng   = warp & 3;    // output group (16 W + 16 L cols)

    const int seg_start = g_off[t];
    const int seg_end   = g_off[t + 1];
    const int stride    = GRIDX * TILE_M;

    const u32 aBase[2] = { smem_u32(sm), smem_u32(sm + F_A1) };

    // ldmatrix lane offset: tile = lane>>3 selects (row+8?, col+4?)
    //   trow = (lane&7) + ((lane>>3)&1)*8 ; tcol4 = (lane>>4)&1 -> +16 bytes
    const u32 lm_off = (u32)(((lane & 7) + ((lane >> 3) & 1) * 8) * (ASTRIDE * 4)
                             + ((lane >> 4) & 1) * 16);

    // fill B_s raw (cvt at fragment preload): 128 rows x 16 float4
    for (int i = tid; i < 128 * 16; i += 256) {
        int row = i >> 4;
        int c4  = i & 15;
        const float* src = (row < 64) ? (layer1 + t * 4096 + row * 64)
                                      : (lin_w + (row - 64) * 64);
        *(float4*)&B_s[row * ASTRIDE + c4 * 4] = ((const float4*)src)[c4];
    }
    if (tid < 64) sBias[tid] = lin_b[tid];

    // gather mapping: edge = tid>>2, quarter = tid&3 (4 x 16B per thread)
    const int ge_e = tid >> 2;
    const int ge_q = tid & 3;

    // issue tile 0 into buf0 (+ perm stage)
    int base0 = seg_start + blockIdx.x * TILE_M;
    if (base0 < seg_end) {
        int gidx = base0 + ge_e;
        bool v = (gidx < seg_end);
        int gc = v ? gidx : seg_end - 1;
        int p = g_perm[gc];
        if (ge_q == 0) sPermB[ge_e] = v ? p : -1;
        const char* src = (const char*)(desc + p * 64 + ge_q * 16);
        u32 dst = aBase[0] + ge_e * (ASTRIDE * 4) + ge_q * 64;
        CP_ASYNC16(dst, src);
        CP_ASYNC16(dst + 16, src + 16);
        CP_ASYNC16(dst + 32, src + 32);
        CP_ASYNC16(dst + 48, src + 48);
    }
    CP_COMMIT();
    __syncthreads();

    // preload B fragments: bf[nb][kc][2]; nb 0-1 = W blocks, 2-3 = L blocks
    u32 bf[4][8][2];
    #pragma unroll
    for (int nb = 0; nb < 4; nb++) {
        int cb  = (nb < 2) ? (ng * 2 + nb) : (8 + ng * 2 + (nb - 2));
        int row = cb * 8 + g;
        #pragma unroll
        for (int kc = 0; kc < 8; kc++) {
            bf[nb][kc][0] = to_tf32(B_s[row * ASTRIDE + kc * 8 + tig]);
            bf[nb][kc][1] = to_tf32(B_s[row * ASTRIDE + kc * 8 + tig + 4]);
        }
    }

    int buf = 0;
    for (int base = base0; base < seg_end; base += stride) {
        // issue next tile into the other buffer
        int nbase = base + stride;
        if (nbase < seg_end) {
            int gidx = nbase + ge_e;
            bool v = (gidx < seg_end);
            int gc = v ? gidx : seg_end - 1;
            int p = g_perm[gc];
            if (ge_q == 0) sPermB[(buf ^ 1) * 64 + ge_e] = v ? p : -1;
            const char* src = (const char*)(desc + p * 64 + ge_q * 16);
            u32 dst = aBase[buf ^ 1] + ge_e * (ASTRIDE * 4) + ge_q * 64;
            CP_ASYNC16(dst, src);
            CP_ASYNC16(dst + 16, src + 16);
            CP_ASYNC16(dst + 32, src + 32);
            CP_ASYNC16(dst + 48, src + 48);
        }
        CP_COMMIT();
        CP_WAIT1();        // current tile's group complete
        __syncthreads();

        // in-place tf32 conversion of this tile (each thread: its 16 floats)
        {
            float4* ap = (float4*)(sm + (buf ? F_A1 : 0)
                                   + ge_e * ASTRIDE + ge_q * 16);
            #pragma unroll
            for (int i = 0; i < 4; i++) {
                float4 v = ap[i];
                v.x = __uint_as_float(to_tf32(v.x));
                v.y = __uint_as_float(to_tf32(v.y));
                v.z = __uint_as_float(to_tf32(v.z));
                v.w = __uint_as_float(to_tf32(v.w));
                ap[i] = v;
            }
        }
        __syncthreads();

        const u32   aCur = aBase[buf];
        const int*  perm = sPermB + buf * 64;

        #pragma unroll
        for (int mc = 0; mc < 2; mc++) {
            const u32 abase_mc = aCur + (mg * 32 + mc * 16) * (ASTRIDE * 4) + lm_off;
            float d[4][4];
            #pragma unroll
            for (int nb = 0; nb < 4; nb++)
                #pragma unroll
                for (int c = 0; c < 4; c++) d[nb][c] = 0.f;

            #pragma unroll
            for (int kc = 0; kc < 8; kc++) {
                u32 a0, a1, a2, a3;
                ldm4(a0, a1, a2, a3, abase_mc + kc * 32);
                #pragma unroll
                for (int nb = 0; nb < 4; nb++)
                    mma8(d[nb], a0, a1, a2, a3, bf[nb][kc][0], bf[nb][kc][1]);
            }

            int eloc = mg * 32 + mc * 16 + g;
            int p0 = perm[eloc];
            int p1 = perm[eloc + 8];
            #pragma unroll
            for (int nb = 0; nb < 2; nb++) {
                int o = ng * 16 + nb * 8 + tig * 2;
                float b0 = sBias[o], b1 = sBias[o + 1];
                if (p0 >= 0) {
                    float2 v;
                    v.x = tanh_ex(d[nb][0]) + d[nb + 2][0] + b0;
                    v.y = tanh_ex(d[nb][1]) + d[nb + 2][1] + b1;
                    *(float2*)&out[p0 * 64 + o] = v;
                }
                if (p1 >= 0) {
                    float2 v;
                    v.x = tanh_ex(d[nb][2]) + d[nb + 2][2] + b0;
                    v.y = tanh_ex(d[nb][3]) + d[nb + 2][3] + b1;
                    *(float2*)&out[p1 * 64 + o] = v;
                }
            }
        }
        __syncthreads();   // A[buf]/perm[buf] consumed before refill
        buf ^= 1;
    }
    CP_WAIT0();            // drain outstanding groups before exit
}

// ---------------- launch ----------------

extern "C" void kernel_launch(void* const* d_in, const int* in_sizes, int n_in,
                              void* d_out, int out_size) {
    const int*   bij    = (const int*)d_in[0];
    const float* desc   = (const float*)d_in[1];
    const float* layer1 = (const float*)d_in[2];
    const float* lin_w  = (const float*)d_in[3];
    const float* lin_b  = (const float*)d_in[4];
    float*       out    = (float*)d_out;
    int n = in_sizes[0];
    if (n > MAX_E) n = MAX_E;

    static int smem_set = 0;
    if (!smem_set) {
        cudaFuncSetAttribute(k_gemm, cudaFuncAttributeMaxDynamicSharedMemorySize,
                             SMEM_BYTES);
        smem_set = 1;
    }

    k_hist<<<NB_HIST, 1024>>>(bij, n);
    k_prefix<<<1, 32>>>();
    k_scatter<<<(n + 1023) / 1024, 1024>>>(bij, n);
    k_gemm<<<dim3(GRIDX, NTYPE), 256, SMEM_BYTES>>>(desc, layer1, lin_w, lin_b, out);
}